// round 15
// baseline (speedup 1.0000x reference)
#include <cuda_runtime.h>
#include <cuda_fp16.h>
#include <cstdint>

#define N_MAX 8192
#define D_MAX 256
#define BM 128
#define BN 128
#define BK 32                     // f16 K per stage
#define NBUF 3
#define NSTAGE 8                  // 256/32
#define NTHREADS 256
#define MARGIN 0.5f

__device__ __half g_xh[N_MAX * D_MAX];
__device__ float g_sq[N_MAX];
__device__ int   g_is64;

// dynamic smem layout (bytes): stage = A(8KB) + B(8KB)
#define STAGE_BYTES  16384
#define SM_SQI   (NBUF * STAGE_BYTES)               // 49152
#define SM_SQJ   (SM_SQI + BM * 4)
#define SM_TI    (SM_SQJ + BN * 4)
#define SM_TJ    (SM_TI + BM * 4)
#define SM_RED   (SM_TJ + BN * 4)
#define SM_TOTAL (SM_RED + NTHREADS * 4)            // ~51.2 KB -> 3 CTAs/SM

__device__ __forceinline__ uint32_t smem_u32(const void* p) {
    uint32_t a;
    asm("{ .reg .u64 t; cvta.to.shared.u64 t, %1; cvt.u32.u64 %0, t; }" : "=r"(a) : "l"(p));
    return a;
}

// ---------------------------------------------------------------------------
// fused prelim: zero out + int64 detect + exact fp32 norms + f16 copy
// ---------------------------------------------------------------------------
__global__ void cvtsq_kernel(const float* __restrict__ x,
                             const unsigned int* __restrict__ t, int n,
                             float* __restrict__ out) {
    if (blockIdx.x == 0 && threadIdx.x < 32) {
        int lane = threadIdx.x;
        unsigned bad = t[2 * lane + 1] | t[2 * (lane + 32) + 1];
        unsigned ball = __ballot_sync(0xffffffffu, bad != 0u);
        if (lane == 0) { g_is64 = (ball == 0u); out[0] = 0.0f; }
    }

    int row  = blockIdx.x * (blockDim.x >> 5) + (threadIdx.x >> 5);
    int lane = threadIdx.x & 31;
    if (row >= n) return;
    const float* p = x + (size_t)row * D_MAX;

    float4 v0 = *(const float4*)(p + lane * 4);
    float4 v1 = *(const float4*)(p + 128 + lane * 4);

    float s = v0.x * v0.x + v0.y * v0.y + v0.z * v0.z + v0.w * v0.w
            + v1.x * v1.x + v1.y * v1.y + v1.z * v1.z + v1.w * v1.w;
    #pragma unroll
    for (int o = 16; o > 0; o >>= 1) s += __shfl_xor_sync(0xffffffffu, s, o);
    if (lane == 0) g_sq[row] = s;

    __half* dst = g_xh + (size_t)row * D_MAX;
    *(__half2*)(dst + lane * 4)           = __floats2half2_rn(v0.x, v0.y);
    *(__half2*)(dst + lane * 4 + 2)       = __floats2half2_rn(v0.z, v0.w);
    *(__half2*)(dst + 128 + lane * 4)     = __floats2half2_rn(v1.x, v1.y);
    *(__half2*)(dst + 128 + lane * 4 + 2) = __floats2half2_rn(v1.z, v1.w);
}

// ---------------------------------------------------------------------------
// f16 mma.sync fused gram + loss. CTA 128x128, 8 warps (2m x 4n), warp 64x32.
// 3 CTAs/SM (6 warps/SMSP) via small footprint: BK=32 stages, 3 buffers,
// wait_group 1 lookahead, single frag buffer (inter-warp latency hiding).
// smem rows: 64B stride; chunk c of row r at r*64 + ((c^(r&3))<<4).
// addr(ks) = base ^ (ks<<5)  [ch = coff ^ 2ks; XOR distributes].
// ---------------------------------------------------------------------------
__global__ __launch_bounds__(NTHREADS, 3)
void loss_kernel(const void* __restrict__ tgt_raw, float* __restrict__ out,
                 int nt, float scale) {
    // triangular decode t -> (bi, bj), bj >= bi (validated R5-R11)
    const int t = blockIdx.x;
    int b = (int)((2.0f * nt + 1.0f -
                   sqrtf((2.0f * nt + 1.0f) * (2.0f * nt + 1.0f) - 8.0f * t)) * 0.5f);
    if (b < 0) b = 0;
    if (b > nt - 1) b = nt - 1;
    while (b + 1 <= nt - 1 && (b + 1) * nt - ((b + 1) * b) / 2 <= t) b++;
    while (b * nt - (b * (b - 1)) / 2 > t) b--;
    const int bi = b;
    const int bj = bi + (t - (bi * nt - (bi * (bi - 1)) / 2));

    extern __shared__ char smem[];
    float* s_sqi = (float*)(smem + SM_SQI);
    float* s_sqj = (float*)(smem + SM_SQJ);
    int*   s_ti  = (int*)(smem + SM_TI);
    int*   s_tj  = (int*)(smem + SM_TJ);
    float* s_red = (float*)(smem + SM_RED);

    const int tid  = threadIdx.x;
    const int wid  = tid >> 5;
    const int lane = tid & 31;
    const int iBase = bi * BM;
    const int jBase = bj * BN;

    const uint32_t smem_tiles = smem_u32(smem);
    const __half* xa = g_xh + (size_t)iBase * D_MAX;
    const __half* xb = g_xh + (size_t)jBase * D_MAX;

    // stage = 16KB: A 512 chunks (2/thread) + B 512 (2/thread); row=idx>>2, c=idx&3
    auto load_stage = [&](int S) {
        const int k0 = S * BK;
        const uint32_t sA = smem_tiles + (S % NBUF) * STAGE_BYTES;
        const uint32_t sB = sA + BM * BK * 2;
        #pragma unroll
        for (int u = 0; u < 2; u++) {
            int idx = tid * 2 + u;
            int row = idx >> 2;
            int c   = idx & 3;
            uint32_t sw = row * 64 + (((c ^ (row & 3)) & 3) << 4);
            asm volatile("cp.async.cg.shared.global [%0], [%1], 16;"
                         :: "r"(sA + sw), "l"((const void*)(xa + row * D_MAX + k0 + c * 8)) : "memory");
            asm volatile("cp.async.cg.shared.global [%0], [%1], 16;"
                         :: "r"(sB + sw), "l"((const void*)(xb + row * D_MAX + k0 + c * 8)) : "memory");
        }
        asm volatile("cp.async.commit_group;" ::: "memory");
    };

    load_stage(0);
    load_stage(1);

    // metadata (overlaps cp.async)
    {
        const long long* t64p = (const long long*)tgt_raw;
        const int*       t32p = (const int*)tgt_raw;
        const bool is64 = (g_is64 != 0);
        if (tid < BM) {
            s_sqi[tid] = g_sq[iBase + tid];
            s_ti[tid]  = is64 ? (int)t64p[iBase + tid] : t32p[iBase + tid];
        } else {
            int tt = tid - BM;
            s_sqj[tt] = g_sq[jBase + tt];
            s_tj[tt]  = is64 ? (int)t64p[jBase + tt] : t32p[jBase + tt];
        }
    }

    // warp grid 2m x 4n; warp tile 64 x 32
    const int mbase = (wid >> 2) * 64;
    const int nbase = (wid & 3) * 32;

    const int a_roff = ((lane >> 3) & 1) * 8 + (lane & 7);
    const int a_coff = (lane >> 4);
    const int b_roff = ((lane >> 4) & 1) * 8 + (lane & 7);
    const int b_coff = ((lane >> 3) & 1);

    uint32_t acc[4][4][2];
    #pragma unroll
    for (int mt = 0; mt < 4; mt++)
        #pragma unroll
        for (int ntl = 0; ntl < 4; ntl++) { acc[mt][ntl][0] = 0u; acc[mt][ntl][1] = 0u; }

    #pragma unroll
    for (int S = 0; S < NSTAGE; S++) {
        // stage S resident (one younger group may still be in flight)
        if (S + 1 < NSTAGE) { asm volatile("cp.async.wait_group 1;" ::: "memory"); }
        else                { asm volatile("cp.async.wait_group 0;" ::: "memory"); }
        __syncthreads();   // also: all warps are past stage S-1 -> buf (S+2)%3 free
        if (S + 2 < NSTAGE) load_stage(S + 2);

        const uint32_t sA = smem_tiles + (S % NBUF) * STAGE_BYTES;
        const uint32_t sB = sA + BM * BK * 2;

        // base addresses at ks=0; addr(ks) = base ^ (ks<<5)
        uint32_t abase[4], bbase[2];
        #pragma unroll
        for (int mt = 0; mt < 4; mt++) {
            int r = mbase + mt * 16 + a_roff;
            abase[mt] = sA + r * 64 + (((a_coff ^ (r & 3)) & 3) << 4);
        }
        #pragma unroll
        for (int p = 0; p < 2; p++) {
            int r = nbase + p * 16 + b_roff;
            bbase[p] = sB + r * 64 + (((b_coff ^ (r & 3)) & 3) << 4);
        }

        #pragma unroll
        for (int ks = 0; ks < 2; ks++) {          // two k16 steps per stage
            uint32_t aF[4][4], bF[4][2];
            #pragma unroll
            for (int mt = 0; mt < 4; mt++)
                asm volatile("ldmatrix.sync.aligned.m8n8.x4.shared.b16 {%0,%1,%2,%3}, [%4];"
                             : "=r"(aF[mt][0]), "=r"(aF[mt][1]),
                               "=r"(aF[mt][2]), "=r"(aF[mt][3])
                             : "r"(abase[mt] ^ (unsigned)(ks << 5)));
            #pragma unroll
            for (int p = 0; p < 2; p++)
                asm volatile("ldmatrix.sync.aligned.m8n8.x4.shared.b16 {%0,%1,%2,%3}, [%4];"
                             : "=r"(bF[2 * p][0]), "=r"(bF[2 * p][1]),
                               "=r"(bF[2 * p + 1][0]), "=r"(bF[2 * p + 1][1])
                             : "r"(bbase[p] ^ (unsigned)(ks << 5)));
            #pragma unroll
            for (int mt = 0; mt < 4; mt++)
                #pragma unroll
                for (int ntl = 0; ntl < 4; ntl++)
                    asm volatile(
                        "mma.sync.aligned.m16n8k16.row.col.f16.f16.f16.f16 "
                        "{%0,%1}, {%2,%3,%4,%5}, {%6,%7}, {%0,%1};"
                        : "+r"(acc[mt][ntl][0]), "+r"(acc[mt][ntl][1])
                        : "r"(aF[mt][0]), "r"(aF[mt][1]),
                          "r"(aF[mt][2]), "r"(aF[mt][3]),
                          "r"(bF[ntl][0]), "r"(bF[ntl][1]));
        }
    }

    // epilogue: unpack f16 acc -> dist -> hinge/mask -> sum over gi < gj
    const int gid = lane >> 2;
    const int tig = lane & 3;
    const bool diag = (bi == bj);
    float lsum = 0.0f;
    #pragma unroll
    for (int mt = 0; mt < 4; mt++) {
        #pragma unroll
        for (int ntl = 0; ntl < 4; ntl++) {
            #pragma unroll
            for (int h = 0; h < 2; h++) {
                float2 gp = __half22float2(*(const __half2*)&acc[mt][ntl][h]);
                int m = mbase + mt * 16 + gid + h * 8;
                float sqm = s_sqi[m];
                int   tm  = s_ti[m];
                #pragma unroll
                for (int q = 0; q < 2; q++) {
                    int nn = nbase + ntl * 8 + 2 * tig + q;
                    float g    = q ? gp.y : gp.x;
                    float dist = fmaf(-2.0f, g, sqm + s_sqj[nn]);
                    float val  = (tm == s_tj[nn]) ? dist : fmaxf(MARGIN - dist, 0.0f);
                    if (!diag || (m < nn)) lsum += val;
                }
            }
        }
    }

    s_red[tid] = lsum;
    __syncthreads();
    #pragma unroll
    for (int s = NTHREADS / 2; s > 32; s >>= 1) {
        if (tid < s) s_red[tid] += s_red[tid + s];
        __syncthreads();
    }
    if (tid < 32) {
        float v = s_red[tid] + s_red[tid + 32];
        #pragma unroll
        for (int o = 16; o > 0; o >>= 1) v += __shfl_xor_sync(0xffffffffu, v, o);
        if (tid == 0) atomicAdd(out, v * scale);
    }
}

extern "C" void kernel_launch(void* const* d_in, const int* in_sizes, int n_in,
                              void* d_out, int out_size) {
    const float* x   = (const float*)d_in[0];
    const void*  tgt = d_in[1];
    float*       out = (float*)d_out;

    int n = in_sizes[1];            // 8192
    int nt = n / BM;                // 64
    int ntri = nt * (nt + 1) / 2;   // 2080

    static int smem_set = 0;
    if (!smem_set) {
        cudaFuncSetAttribute(loss_kernel, cudaFuncAttributeMaxDynamicSharedMemorySize, SM_TOTAL);
        smem_set = 1;
    }

    cvtsq_kernel<<<(n + 7) / 8, 256>>>(x, (const unsigned int*)tgt, n, out);

    float scale = (float)(1.0 / ((double)n * ((double)n - 1.0)));
    loss_kernel<<<ntri, NTHREADS, SM_TOTAL>>>(tgt, out, nt, scale);
}